// round 12
// baseline (speedup 1.0000x reference)
#include <cuda_runtime.h>
#include <cuda_bf16.h>
#include <cstdint>

// Problem constants
#define N_ROWS 16384
#define DIM    256
#define K_CODES 8192

#define BM 128                    // rows per CTA
#define BN 128                    // codes per tile
#define YSPLIT 8                  // code splits across blockIdx.y
#define TILES_PER_Y (K_CODES / YSPLIT / BN)   // 8 tiles of 128 codes

#define MARGIN 0.125f             // >= 2 * worst-case bf16 dist error (2*eps_d ~ 0.122)
#define CAND_CAP (8u * 1024u * 1024u)
#define G2_BLOCKS (N_ROWS / 8)

// ---------------------------------------------------------------------------
// Device scratch (no cudaMalloc allowed)
// ---------------------------------------------------------------------------
__device__ unsigned long long g_best[N_ROWS];
__device__ unsigned g_rowmin[N_ROWS];            // running approx row min (float bits)
__device__ __align__(16) float g_zsq[N_ROWS];
__device__ __align__(16) float g_esq[K_CODES];
__device__ float g_partial[G2_BLOCKS];
__device__ __align__(16) __nv_bfloat16 g_zb[N_ROWS * DIM];
__device__ __align__(16) __nv_bfloat16 g_cbb[K_CODES * DIM];
__device__ unsigned g_cand[CAND_CAP];
__device__ unsigned g_ncand;

// ---------------------------------------------------------------------------
// PTX helpers (baseline sm_80+ only — compute_103 has no 'a' features)
// ---------------------------------------------------------------------------
__device__ __forceinline__ void ldsm_x4(unsigned* r, unsigned addr) {
    asm volatile("ldmatrix.sync.aligned.m8n8.x4.shared.b16 {%0,%1,%2,%3}, [%4];"
                 : "=r"(r[0]), "=r"(r[1]), "=r"(r[2]), "=r"(r[3]) : "r"(addr));
}
__device__ __forceinline__ void mma_bf16(float* c, const unsigned* a, const unsigned* b) {
    asm volatile(
        "mma.sync.aligned.m16n8k16.row.col.f32.bf16.bf16.f32 "
        "{%0,%1,%2,%3}, {%4,%5,%6,%7}, {%8,%9}, {%0,%1,%2,%3};"
        : "+f"(c[0]), "+f"(c[1]), "+f"(c[2]), "+f"(c[3])
        : "r"(a[0]), "r"(a[1]), "r"(a[2]), "r"(a[3]), "r"(b[0]), "r"(b[1]));
}
#define CP_ASYNC16(dst, src) \
    asm volatile("cp.async.cg.shared.global [%0], [%1], 16;" :: "r"(dst), "l"(src) : "memory")
#define CP_ASYNC_COMMIT() asm volatile("cp.async.commit_group;" ::: "memory")
#define CP_ASYNC_WAIT0()  asm volatile("cp.async.wait_group 0;" ::: "memory")

__device__ __forceinline__ uint32_t smem_u32(const void* p) {
    uint32_t a;
    asm("{ .reg .u64 t; cvta.to.shared.u64 t, %1; cvt.u32.u64 %0, t; }"
        : "=r"(a) : "l"(p));
    return a;
}

// Row-major smem tile: row stride 512B, 16B granule g stored at (g ^ (r&7)).
__device__ __forceinline__ uint32_t sw_off(int r, int g) {
    return (uint32_t)(r * 512 + (((unsigned)(g ^ (r & 7))) << 4));
}

// SMEM layout (dynamic)
#define SMEM_ROWMIN 0                 // 128 u32
#define SMEM_CUT    512               // 128 f32
#define SMEM_ESQ    1024              // 2 x 128 f32 (per B buffer)
#define SMEM_A      2048              // 64KB
#define SMEM_B0     (2048 + 65536)
#define SMEM_BSZ    65536
#define SMEM_TOTAL  (SMEM_B0 + 2 * SMEM_BSZ)   // 198656

extern __shared__ char smem_raw[];

// ---------------------------------------------------------------------------
// Approx bf16 HMMA GEMM + row-global-min filter + candidate append.
// 512 threads = 16 warps (4x4 grid of 32x32 warp tiles). B double-buffered.
// Epilogue: single pass with cut published at tile start from the running
// row minimum through the PREVIOUS tile (one-tile-stale cut is provably safe:
// cut = stale_min + MARGIN >= d_min + eps >= d~_winner). Tile 0 keeps the
// two-pass form (a stale cut there would be +inf -> candidate flood).
// ---------------------------------------------------------------------------
__global__ __launch_bounds__(512, 1)
void approx_gemm_kernel() {
    const int tid  = threadIdx.x;
    const int lane = tid & 31;
    const int warp = tid >> 5;
    const int wm = (warp & 3) * 32;     // warp m offset (4 rows of warps)
    const int wn = (warp >> 2) * 32;    // warp n offset (4 cols of warps)
    const int row0  = blockIdx.x * BM;
    const int cbase = blockIdx.y * (K_CODES / YSPLIT);

    unsigned* rowmin_s = (unsigned*)(smem_raw + SMEM_ROWMIN);
    float*    cut_s    = (float*)(smem_raw + SMEM_CUT);
    float*    esq_s    = (float*)(smem_raw + SMEM_ESQ);
    const uint32_t sbase  = smem_u32(smem_raw);
    const uint32_t a_base = sbase + SMEM_A;

    // ---- Prologue: A (64KB), B tile 0 (64KB), esq(0), rowmin init ----
    #pragma unroll
    for (int i = 0; i < 8; i++) {
        int id = i * 512 + tid;
        int r = id >> 5, g = id & 31;
        CP_ASYNC16(a_base + sw_off(r, g),
                   (const void*)(g_zb + ((size_t)(row0 + r) << 8) + g * 8));
    }
    #pragma unroll
    for (int i = 0; i < 8; i++) {
        int id = i * 512 + tid;
        int r = id >> 5, g = id & 31;
        CP_ASYNC16(sbase + SMEM_B0 + sw_off(r, g),
                   (const void*)(g_cbb + ((size_t)(cbase + r) << 8) + g * 8));
    }
    if (tid < 32)
        CP_ASYNC16(sbase + SMEM_ESQ + tid * 16, (const void*)(g_esq + cbase + tid * 4));
    if (tid < 128) rowmin_s[tid] = 0xFFFFFFFFu;
    CP_ASYNC_COMMIT();

    // acc[mt][nt][q]: row = wm + mt*16 + (lane>>2) + (q>>1)*8
    //                 col = wn + nt*8 + 2*(lane&3) + (q&1)
    const int rbase = lane >> 2;
    float zr[4];
    #pragma unroll
    for (int mt = 0; mt < 2; mt++)
        #pragma unroll
        for (int fr = 0; fr < 2; fr++)
            zr[mt * 2 + fr] = g_zsq[row0 + wm + mt * 16 + rbase + fr * 8];

    // ldmatrix lane addressing (proven layouts, rounds 4/6/8/11)
    const int a_r[2] = { wm + (lane & 15), wm + 16 + (lane & 15) };
    const int a_g0 = lane >> 4;
    int b_r[2];
    #pragma unroll
    for (int p = 0; p < 2; p++)
        b_r[p] = wn + p * 16 + ((lane >> 4) & 1) * 8 + (lane & 7);
    const int b_g0 = (lane >> 3) & 1;
    const int ncol = 2 * (lane & 3);

    CP_ASYNC_WAIT0();
    __syncthreads();

    #pragma unroll 1
    for (int ct = 0; ct < TILES_PER_Y; ct++) {
        const int buf = ct & 1;
        const uint32_t bbase = sbase + SMEM_B0 + buf * SMEM_BSZ;
        const int code0 = cbase + ct * BN;

        // Tile start (ct>0): publish cut from rowmin through tile ct-1,
        // merged with the global running row min; reset rowmin for this tile.
        if (ct > 0 && tid < 128) {
            unsigned mine = rowmin_s[tid];
            unsigned old  = atomicMin(&g_rowmin[row0 + tid], mine);
            unsigned cur  = (old < mine) ? old : mine;
            cut_s[tid] = __uint_as_float(cur) + MARGIN;
            rowmin_s[tid] = 0xFFFFFFFFu;
        }

        // Prefetch B tile ct+1 + its esq into the other buffer
        if (ct + 1 < TILES_PER_Y) {
            #pragma unroll
            for (int i = 0; i < 8; i++) {
                int id = i * 512 + tid;
                int r = id >> 5, g = id & 31;
                CP_ASYNC16(sbase + SMEM_B0 + (buf ^ 1) * SMEM_BSZ + sw_off(r, g),
                           (const void*)(g_cbb + ((size_t)(code0 + BN + r) << 8) + g * 8));
            }
            if (tid < 32)
                CP_ASYNC16(sbase + SMEM_ESQ + (buf ^ 1) * 512 + tid * 16,
                           (const void*)(g_esq + code0 + BN + tid * 4));
            CP_ASYNC_COMMIT();
        }

        // ---- MMA: 16 ksteps over K=256, warp tile 32x32 ----
        float acc[2][4][4];
        #pragma unroll
        for (int mt = 0; mt < 2; mt++)
            #pragma unroll
            for (int nt = 0; nt < 4; nt++)
                #pragma unroll
                for (int q = 0; q < 4; q++) acc[mt][nt][q] = 0.f;

        #pragma unroll
        for (int ks = 0; ks < 16; ks++) {
            unsigned a[2][4], b[4][2];
            #pragma unroll
            for (int mt = 0; mt < 2; mt++)
                ldsm_x4(a[mt], a_base + sw_off(a_r[mt], ks * 2 + a_g0));
            #pragma unroll
            for (int p = 0; p < 2; p++) {
                unsigned t[4];
                ldsm_x4(t, bbase + sw_off(b_r[p], ks * 2 + b_g0));
                b[p * 2 + 0][0] = t[0]; b[p * 2 + 0][1] = t[1];
                b[p * 2 + 1][0] = t[2]; b[p * 2 + 1][1] = t[3];
            }
            #pragma unroll
            for (int mt = 0; mt < 2; mt++)
                #pragma unroll
                for (int nt = 0; nt < 4; nt++)
                    mma_bf16(acc[mt][nt], a[mt], b[nt]);
        }

        __syncthreads();   // barrier A: cut_s (ct>0) visible to all warps

        if (ct == 0) {
            // ---- Tile 0: two-pass (no valid stale cut exists yet) ----
            #pragma unroll
            for (int mt = 0; mt < 2; mt++) {
                #pragma unroll
                for (int fr = 0; fr < 2; fr++) {
                    int rl = wm + mt * 16 + rbase + fr * 8;
                    float zv = zr[mt * 2 + fr];
                    float mn = 3.4e38f;
                    #pragma unroll
                    for (int nt = 0; nt < 4; nt++) {
                        #pragma unroll
                        for (int c = 0; c < 2; c++) {
                            float d = fmaf(-2.0f, acc[mt][nt][fr * 2 + c],
                                           zv + esq_s[buf * 128 + wn + nt * 8 + ncol + c]);
                            mn = fminf(mn, d);
                        }
                    }
                    atomicMin(&rowmin_s[rl], __float_as_uint(mn));
                }
            }
            __syncthreads();
            if (tid < 128) {
                unsigned mine = rowmin_s[tid];
                unsigned old  = atomicMin(&g_rowmin[row0 + tid], mine);
                unsigned cur  = (old < mine) ? old : mine;
                cut_s[tid] = __uint_as_float(cur) + MARGIN;
                // no reset: tile-1 start re-merges (idempotent) and resets
            }
            __syncthreads();
            #pragma unroll
            for (int mt = 0; mt < 2; mt++) {
                #pragma unroll
                for (int fr = 0; fr < 2; fr++) {
                    int rl = wm + mt * 16 + rbase + fr * 8;
                    float zv  = zr[mt * 2 + fr];
                    float cut = cut_s[rl];
                    unsigned rowg = (unsigned)(row0 + rl);
                    #pragma unroll
                    for (int nt = 0; nt < 4; nt++) {
                        #pragma unroll
                        for (int c = 0; c < 2; c++) {
                            float d = fmaf(-2.0f, acc[mt][nt][fr * 2 + c],
                                           zv + esq_s[buf * 128 + wn + nt * 8 + ncol + c]);
                            if (d <= cut) {
                                unsigned pos = atomicAdd(&g_ncand, 1u);
                                if (pos < CAND_CAP)
                                    g_cand[pos] = (rowg << 13) |
                                                  (unsigned)(code0 + wn + nt * 8 + ncol + c);
                            }
                        }
                    }
                }
            }
        } else {
            // ---- Single pass: append with stale cut, track min for next tile ----
            #pragma unroll
            for (int mt = 0; mt < 2; mt++) {
                #pragma unroll
                for (int fr = 0; fr < 2; fr++) {
                    int rl = wm + mt * 16 + rbase + fr * 8;
                    float zv  = zr[mt * 2 + fr];
                    float cut = cut_s[rl];
                    unsigned rowg = (unsigned)(row0 + rl);
                    float mn = 3.4e38f;
                    #pragma unroll
                    for (int nt = 0; nt < 4; nt++) {
                        #pragma unroll
                        for (int c = 0; c < 2; c++) {
                            float d = fmaf(-2.0f, acc[mt][nt][fr * 2 + c],
                                           zv + esq_s[buf * 128 + wn + nt * 8 + ncol + c]);
                            mn = fminf(mn, d);
                            if (d <= cut) {
                                unsigned pos = atomicAdd(&g_ncand, 1u);
                                if (pos < CAND_CAP)
                                    g_cand[pos] = (rowg << 13) |
                                                  (unsigned)(code0 + wn + nt * 8 + ncol + c);
                            }
                        }
                    }
                    atomicMin(&rowmin_s[rl], __float_as_uint(mn));
                }
            }
        }

        // B(ct+1) resident + rowmin deposits complete before next tile start
        if (ct + 1 < TILES_PER_Y) {
            CP_ASYNC_WAIT0();
            __syncthreads();   // barrier B
        }
    }
}

// ---------------------------------------------------------------------------
// Init
// ---------------------------------------------------------------------------
__global__ void init_kernel() {
    int i = blockIdx.x * blockDim.x + threadIdx.x;
    if (i < N_ROWS) {
        g_best[i]   = 0xFFFFFFFFFFFFFFFFull;
        g_rowmin[i] = 0xFFFFFFFFu;
    }
    if (i == 0) g_ncand = 0u;
}

// ---------------------------------------------------------------------------
// Fused convert + sum-of-squares (warp per row).
// IMPORTANT: the squares are summed in the SAME strided k-order as the
// original sq_kernel so g_zsq/g_esq are byte-identical (they feed exact
// fp32 dist comparisons). bf16 conversion is per-element RN (same bits).
// ---------------------------------------------------------------------------
__global__ void convsq_kernel(const float* __restrict__ z,
                              const float* __restrict__ cb) {
    int warp = (blockIdx.x * blockDim.x + threadIdx.x) >> 5;
    int lane = threadIdx.x & 31;
    if (warp >= N_ROWS + K_CODES) return;
    const float* src;
    __nv_bfloat16* dst;
    if (warp < N_ROWS) {
        src = z + (size_t)warp * DIM;
        dst = g_zb + (size_t)warp * DIM;
    } else {
        src = cb + (size_t)(warp - N_ROWS) * DIM;
        dst = g_cbb + (size_t)(warp - N_ROWS) * DIM;
    }
    float s = 0.f;
    #pragma unroll
    for (int k = 0; k < DIM; k += 32) {
        float v = src[k + lane];
        dst[k + lane] = __float2bfloat16_rn(v);
        s = fmaf(v, v, s);
    }
    #pragma unroll
    for (int o = 16; o > 0; o >>= 1) s += __shfl_xor_sync(0xFFFFFFFFu, s, o);
    if (lane == 0) {
        if (warp < N_ROWS) g_zsq[warp] = s;
        else               g_esq[warp - N_ROWS] = s;
    }
}

// ---------------------------------------------------------------------------
// Exact fp32 re-rank (bit-compatible dist chain; order-independent winner)
// ---------------------------------------------------------------------------
__global__ void rerank_kernel(const float* __restrict__ z, const float* __restrict__ cb) {
    unsigned n = g_ncand;
    if (n > CAND_CAP) n = CAND_CAP;
    unsigned stride = gridDim.x * blockDim.x;
    for (unsigned e = blockIdx.x * blockDim.x + threadIdx.x; e < n; e += stride) {
        unsigned ent = g_cand[e];
        unsigned r = ent >> 13;
        unsigned j = ent & 8191u;
        const float4* zrp = reinterpret_cast<const float4*>(z  + (size_t)r * DIM);
        const float4* crp = reinterpret_cast<const float4*>(cb + (size_t)j * DIM);
        float s = 0.f;
        #pragma unroll 8
        for (int k = 0; k < 64; k++) {
            float4 a = zrp[k];
            float4 b = crp[k];
            s = fmaf(a.x, b.x, s);
            s = fmaf(a.y, b.y, s);
            s = fmaf(a.z, b.z, s);
            s = fmaf(a.w, b.w, s);
        }
        float t = g_zsq[r] + g_esq[j];
        float d = t - 2.0f * s;
        unsigned long long key =
            ((unsigned long long)__float_as_uint(d) << 32) | (unsigned long long)j;
        atomicMin(&g_best[r], key);
    }
}

__global__ void gather_kernel(const float* __restrict__ z,
                              const float* __restrict__ cb,
                              float* __restrict__ out) {
    __shared__ float wsum[8];
    int warpId = threadIdx.x >> 5;
    int lane   = threadIdx.x & 31;
    int r = blockIdx.x * 8 + warpId;

    unsigned idx = (unsigned)(g_best[r] & 0xFFFFFFFFull);
    const float* zrp = z  + (size_t)r * DIM;
    const float* erp = cb + (size_t)idx * DIM;
    float* orow = out + (size_t)r * DIM;

    float s = 0.f;
    #pragma unroll
    for (int k = 0; k < DIM; k += 32) {
        float zv = zrp[k + lane];
        float ev = erp[k + lane];
        orow[k + lane] = zv + (ev - zv);
        float diff = zv - ev;
        s = fmaf(diff, diff, s);
    }
    #pragma unroll
    for (int o = 16; o > 0; o >>= 1) s += __shfl_xor_sync(0xFFFFFFFFu, s, o);
    if (lane == 0) {
        wsum[warpId] = s;
        out[(size_t)N_ROWS * DIM + r] = (float)idx;
    }
    __syncthreads();
    if (threadIdx.x == 0) {
        float t = 0.f;
        #pragma unroll
        for (int w = 0; w < 8; w++) t += wsum[w];
        g_partial[blockIdx.x] = t;
    }
}

__global__ void loss_kernel(float* __restrict__ out) {
    __shared__ float sm[256];
    int t = threadIdx.x;
    float s = 0.f;
    #pragma unroll
    for (int k = 0; k < G2_BLOCKS; k += 256) s += g_partial[k + t];
    sm[t] = s;
    __syncthreads();
    for (int o = 128; o > 0; o >>= 1) {
        if (t < o) sm[t] = sm[t] + sm[t + o];
        __syncthreads();
    }
    if (t == 0) {
        float m = sm[0] / (float)((size_t)N_ROWS * DIM);
        out[(size_t)N_ROWS * DIM + N_ROWS] = m + 0.25f * m;
    }
}

// ---------------------------------------------------------------------------
// Launch
// ---------------------------------------------------------------------------
extern "C" void kernel_launch(void* const* d_in, const int* in_sizes, int n_in,
                              void* d_out, int out_size) {
    const float* z  = (const float*)d_in[0];
    const float* cb = (const float*)d_in[1];
    float* out = (float*)d_out;
    (void)in_sizes; (void)n_in; (void)out_size;

    cudaFuncSetAttribute(approx_gemm_kernel,
                         cudaFuncAttributeMaxDynamicSharedMemorySize, SMEM_TOTAL);

    init_kernel<<<(N_ROWS + 255) / 256, 256>>>();

    int cs_warps = N_ROWS + K_CODES;                   // 24576 rows
    convsq_kernel<<<(cs_warps * 32 + 255) / 256, 256>>>(z, cb);

    dim3 grid(N_ROWS / BM, YSPLIT);      // (128, 8) = 1024 CTAs
    approx_gemm_kernel<<<grid, 512, SMEM_TOTAL>>>();

    rerank_kernel<<<1024, 256>>>(z, cb);
    gather_kernel<<<G2_BLOCKS, 256>>>(z, cb, out);
    loss_kernel<<<1, 256>>>(out);
}

// round 13
// speedup vs baseline: 1.2139x; 1.2139x over previous
#include <cuda_runtime.h>
#include <cuda_bf16.h>
#include <cstdint>

// Problem constants
#define N_ROWS 16384
#define DIM    256
#define K_CODES 8192

#define BM 128                    // rows per CTA
#define BN 128                    // codes per tile
#define YSPLIT 8                  // code splits across blockIdx.y
#define TILES_PER_Y (K_CODES / YSPLIT / BN)   // 8 tiles of 128 codes

#define MARGIN 0.125f             // >= 2 * worst-case bf16 dist error (2*eps_d ~ 0.122)
#define CAND_CAP (8u * 1024u * 1024u)
#define G2_BLOCKS (N_ROWS / 8)

// ---------------------------------------------------------------------------
// Device scratch (no cudaMalloc allowed)
// ---------------------------------------------------------------------------
__device__ unsigned long long g_best[N_ROWS];
__device__ unsigned g_rowmin[N_ROWS];            // running approx row min (float bits)
__device__ __align__(16) float g_zsq[N_ROWS];
__device__ __align__(16) float g_esq[K_CODES];
__device__ float g_partial[G2_BLOCKS];
__device__ __align__(16) __nv_bfloat16 g_zb[N_ROWS * DIM];
__device__ __align__(16) __nv_bfloat16 g_cbb[K_CODES * DIM];
__device__ unsigned long long g_cand[CAND_CAP];  // (dist_bits<<32 | row<<13 | code)
__device__ unsigned g_ncand;

// ---------------------------------------------------------------------------
// PTX helpers (baseline sm_80+ only — compute_103 has no 'a' features)
// ---------------------------------------------------------------------------
__device__ __forceinline__ void ldsm_x4(unsigned* r, unsigned addr) {
    asm volatile("ldmatrix.sync.aligned.m8n8.x4.shared.b16 {%0,%1,%2,%3}, [%4];"
                 : "=r"(r[0]), "=r"(r[1]), "=r"(r[2]), "=r"(r[3]) : "r"(addr));
}
__device__ __forceinline__ void mma_bf16(float* c, const unsigned* a, const unsigned* b) {
    asm volatile(
        "mma.sync.aligned.m16n8k16.row.col.f32.bf16.bf16.f32 "
        "{%0,%1,%2,%3}, {%4,%5,%6,%7}, {%8,%9}, {%0,%1,%2,%3};"
        : "+f"(c[0]), "+f"(c[1]), "+f"(c[2]), "+f"(c[3])
        : "r"(a[0]), "r"(a[1]), "r"(a[2]), "r"(a[3]), "r"(b[0]), "r"(b[1]));
}
#define CP_ASYNC16(dst, src) \
    asm volatile("cp.async.cg.shared.global [%0], [%1], 16;" :: "r"(dst), "l"(src) : "memory")
#define CP_ASYNC_COMMIT() asm volatile("cp.async.commit_group;" ::: "memory")
#define CP_ASYNC_WAIT0()  asm volatile("cp.async.wait_group 0;" ::: "memory")

__device__ __forceinline__ uint32_t smem_u32(const void* p) {
    uint32_t a;
    asm("{ .reg .u64 t; cvta.to.shared.u64 t, %1; cvt.u32.u64 %0, t; }"
        : "=r"(a) : "l"(p));
    return a;
}

// Row-major smem tile: row stride 512B, 16B granule g stored at (g ^ (r&7)).
__device__ __forceinline__ uint32_t sw_off(int r, int g) {
    return (uint32_t)(r * 512 + (((unsigned)(g ^ (r & 7))) << 4));
}

// SMEM layout (dynamic)
#define SMEM_ROWMIN 0                 // 128 u32
#define SMEM_CUT    512               // 128 f32
#define SMEM_ESQ    1024              // 2 x 128 f32 (per B buffer)
#define SMEM_A      2048              // 64KB
#define SMEM_B0     (2048 + 65536)
#define SMEM_BSZ    65536
#define SMEM_TOTAL  (SMEM_B0 + 2 * SMEM_BSZ)   // 198656

extern __shared__ char smem_raw[];

// ---------------------------------------------------------------------------
// Approx bf16 HMMA GEMM + row-global-min filter + candidate append.
// 512 threads = 16 warps (4x4 grid of 32x32 warp tiles). B double-buffered.
// Single-pass epilogue with one-tile-stale cut (provably a superset);
// candidates carry their approx dist so the rerank can prefilter against
// the FINAL row minimum.
// ---------------------------------------------------------------------------
__global__ __launch_bounds__(512, 1)
void approx_gemm_kernel() {
    const int tid  = threadIdx.x;
    const int lane = tid & 31;
    const int warp = tid >> 5;
    const int wm = (warp & 3) * 32;     // warp m offset (4 rows of warps)
    const int wn = (warp >> 2) * 32;    // warp n offset (4 cols of warps)
    const int row0  = blockIdx.x * BM;
    const int cbase = blockIdx.y * (K_CODES / YSPLIT);

    unsigned* rowmin_s = (unsigned*)(smem_raw + SMEM_ROWMIN);
    float*    cut_s    = (float*)(smem_raw + SMEM_CUT);
    float*    esq_s    = (float*)(smem_raw + SMEM_ESQ);
    const uint32_t sbase  = smem_u32(smem_raw);
    const uint32_t a_base = sbase + SMEM_A;

    // ---- Prologue: A (64KB), B tile 0 (64KB), esq(0), rowmin init ----
    #pragma unroll
    for (int i = 0; i < 8; i++) {
        int id = i * 512 + tid;
        int r = id >> 5, g = id & 31;
        CP_ASYNC16(a_base + sw_off(r, g),
                   (const void*)(g_zb + ((size_t)(row0 + r) << 8) + g * 8));
    }
    #pragma unroll
    for (int i = 0; i < 8; i++) {
        int id = i * 512 + tid;
        int r = id >> 5, g = id & 31;
        CP_ASYNC16(sbase + SMEM_B0 + sw_off(r, g),
                   (const void*)(g_cbb + ((size_t)(cbase + r) << 8) + g * 8));
    }
    if (tid < 32)
        CP_ASYNC16(sbase + SMEM_ESQ + tid * 16, (const void*)(g_esq + cbase + tid * 4));
    if (tid < 128) rowmin_s[tid] = 0xFFFFFFFFu;
    CP_ASYNC_COMMIT();

    // acc[mt][nt][q]: row = wm + mt*16 + (lane>>2) + (q>>1)*8
    //                 col = wn + nt*8 + 2*(lane&3) + (q&1)
    const int rbase = lane >> 2;
    float zr[4];
    #pragma unroll
    for (int mt = 0; mt < 2; mt++)
        #pragma unroll
        for (int fr = 0; fr < 2; fr++)
            zr[mt * 2 + fr] = g_zsq[row0 + wm + mt * 16 + rbase + fr * 8];

    // ldmatrix lane addressing (proven layouts, rounds 4/6/8/11/12)
    const int a_r[2] = { wm + (lane & 15), wm + 16 + (lane & 15) };
    const int a_g0 = lane >> 4;
    int b_r[2];
    #pragma unroll
    for (int p = 0; p < 2; p++)
        b_r[p] = wn + p * 16 + ((lane >> 4) & 1) * 8 + (lane & 7);
    const int b_g0 = (lane >> 3) & 1;
    const int ncol = 2 * (lane & 3);

    CP_ASYNC_WAIT0();
    __syncthreads();

    #pragma unroll 1
    for (int ct = 0; ct < TILES_PER_Y; ct++) {
        const int buf = ct & 1;
        const uint32_t bbase = sbase + SMEM_B0 + buf * SMEM_BSZ;
        const int code0 = cbase + ct * BN;

        // Tile start (ct>0): publish cut from rowmin through tile ct-1,
        // merged with the global running row min; reset rowmin for this tile.
        if (ct > 0 && tid < 128) {
            unsigned mine = rowmin_s[tid];
            unsigned old  = atomicMin(&g_rowmin[row0 + tid], mine);
            unsigned cur  = (old < mine) ? old : mine;
            cut_s[tid] = __uint_as_float(cur) + MARGIN;
            rowmin_s[tid] = 0xFFFFFFFFu;
        }

        // Prefetch B tile ct+1 + its esq into the other buffer
        if (ct + 1 < TILES_PER_Y) {
            #pragma unroll
            for (int i = 0; i < 8; i++) {
                int id = i * 512 + tid;
                int r = id >> 5, g = id & 31;
                CP_ASYNC16(sbase + SMEM_B0 + (buf ^ 1) * SMEM_BSZ + sw_off(r, g),
                           (const void*)(g_cbb + ((size_t)(code0 + BN + r) << 8) + g * 8));
            }
            if (tid < 32)
                CP_ASYNC16(sbase + SMEM_ESQ + (buf ^ 1) * 512 + tid * 16,
                           (const void*)(g_esq + code0 + BN + tid * 4));
            CP_ASYNC_COMMIT();
        }

        // ---- MMA: 16 ksteps over K=256, warp tile 32x32 ----
        float acc[2][4][4];
        #pragma unroll
        for (int mt = 0; mt < 2; mt++)
            #pragma unroll
            for (int nt = 0; nt < 4; nt++)
                #pragma unroll
                for (int q = 0; q < 4; q++) acc[mt][nt][q] = 0.f;

        #pragma unroll
        for (int ks = 0; ks < 16; ks++) {
            unsigned a[2][4], b[4][2];
            #pragma unroll
            for (int mt = 0; mt < 2; mt++)
                ldsm_x4(a[mt], a_base + sw_off(a_r[mt], ks * 2 + a_g0));
            #pragma unroll
            for (int p = 0; p < 2; p++) {
                unsigned t[4];
                ldsm_x4(t, bbase + sw_off(b_r[p], ks * 2 + b_g0));
                b[p * 2 + 0][0] = t[0]; b[p * 2 + 0][1] = t[1];
                b[p * 2 + 1][0] = t[2]; b[p * 2 + 1][1] = t[3];
            }
            #pragma unroll
            for (int mt = 0; mt < 2; mt++)
                #pragma unroll
                for (int nt = 0; nt < 4; nt++)
                    mma_bf16(acc[mt][nt], a[mt], b[nt]);
        }

        __syncthreads();   // barrier A: cut_s (ct>0) visible to all warps

        if (ct == 0) {
            // ---- Tile 0: two-pass (no valid stale cut exists yet) ----
            #pragma unroll
            for (int mt = 0; mt < 2; mt++) {
                #pragma unroll
                for (int fr = 0; fr < 2; fr++) {
                    int rl = wm + mt * 16 + rbase + fr * 8;
                    float zv = zr[mt * 2 + fr];
                    float mn = 3.4e38f;
                    #pragma unroll
                    for (int nt = 0; nt < 4; nt++) {
                        #pragma unroll
                        for (int c = 0; c < 2; c++) {
                            float d = fmaf(-2.0f, acc[mt][nt][fr * 2 + c],
                                           zv + esq_s[buf * 128 + wn + nt * 8 + ncol + c]);
                            mn = fminf(mn, d);
                        }
                    }
                    atomicMin(&rowmin_s[rl], __float_as_uint(mn));
                }
            }
            __syncthreads();
            if (tid < 128) {
                unsigned mine = rowmin_s[tid];
                unsigned old  = atomicMin(&g_rowmin[row0 + tid], mine);
                unsigned cur  = (old < mine) ? old : mine;
                cut_s[tid] = __uint_as_float(cur) + MARGIN;
                // no reset: tile-1 start re-merges (idempotent) and resets
            }
            __syncthreads();
            #pragma unroll
            for (int mt = 0; mt < 2; mt++) {
                #pragma unroll
                for (int fr = 0; fr < 2; fr++) {
                    int rl = wm + mt * 16 + rbase + fr * 8;
                    float zv  = zr[mt * 2 + fr];
                    float cut = cut_s[rl];
                    unsigned key0 = ((unsigned)(row0 + rl) << 13);
                    #pragma unroll
                    for (int nt = 0; nt < 4; nt++) {
                        #pragma unroll
                        for (int c = 0; c < 2; c++) {
                            float d = fmaf(-2.0f, acc[mt][nt][fr * 2 + c],
                                           zv + esq_s[buf * 128 + wn + nt * 8 + ncol + c]);
                            if (d <= cut) {
                                unsigned pos = atomicAdd(&g_ncand, 1u);
                                if (pos < CAND_CAP)
                                    g_cand[pos] =
                                        ((unsigned long long)__float_as_uint(d) << 32) |
                                        (unsigned long long)(key0 |
                                            (unsigned)(code0 + wn + nt * 8 + ncol + c));
                            }
                        }
                    }
                }
            }
        } else {
            // ---- Single pass: append with stale cut, track min for next tile ----
            #pragma unroll
            for (int mt = 0; mt < 2; mt++) {
                #pragma unroll
                for (int fr = 0; fr < 2; fr++) {
                    int rl = wm + mt * 16 + rbase + fr * 8;
                    float zv  = zr[mt * 2 + fr];
                    float cut = cut_s[rl];
                    unsigned key0 = ((unsigned)(row0 + rl) << 13);
                    float mn = 3.4e38f;
                    #pragma unroll
                    for (int nt = 0; nt < 4; nt++) {
                        #pragma unroll
                        for (int c = 0; c < 2; c++) {
                            float d = fmaf(-2.0f, acc[mt][nt][fr * 2 + c],
                                           zv + esq_s[buf * 128 + wn + nt * 8 + ncol + c]);
                            mn = fminf(mn, d);
                            if (d <= cut) {
                                unsigned pos = atomicAdd(&g_ncand, 1u);
                                if (pos < CAND_CAP)
                                    g_cand[pos] =
                                        ((unsigned long long)__float_as_uint(d) << 32) |
                                        (unsigned long long)(key0 |
                                            (unsigned)(code0 + wn + nt * 8 + ncol + c));
                            }
                        }
                    }
                    atomicMin(&rowmin_s[rl], __float_as_uint(mn));
                }
            }
        }

        // B(ct+1) resident + rowmin deposits complete before next tile start
        if (ct + 1 < TILES_PER_Y) {
            CP_ASYNC_WAIT0();
            __syncthreads();   // barrier B
        }
    }

    // Final tile's rowmin must reach g_rowmin (rerank prefilters against it)
    __syncthreads();
    if (tid < 128) atomicMin(&g_rowmin[row0 + tid], rowmin_s[tid]);
}

// ---------------------------------------------------------------------------
// Init
// ---------------------------------------------------------------------------
__global__ void init_kernel() {
    int i = blockIdx.x * blockDim.x + threadIdx.x;
    if (i < N_ROWS) {
        g_best[i]   = 0xFFFFFFFFFFFFFFFFull;
        g_rowmin[i] = 0xFFFFFFFFu;
    }
    if (i == 0) g_ncand = 0u;
}

// ---------------------------------------------------------------------------
// Fused convert + sum-of-squares (warp per row), strided k-order preserved.
// ---------------------------------------------------------------------------
__global__ void convsq_kernel(const float* __restrict__ z,
                              const float* __restrict__ cb) {
    int warp = (blockIdx.x * blockDim.x + threadIdx.x) >> 5;
    int lane = threadIdx.x & 31;
    if (warp >= N_ROWS + K_CODES) return;
    const float* src;
    __nv_bfloat16* dst;
    if (warp < N_ROWS) {
        src = z + (size_t)warp * DIM;
        dst = g_zb + (size_t)warp * DIM;
    } else {
        src = cb + (size_t)(warp - N_ROWS) * DIM;
        dst = g_cbb + (size_t)(warp - N_ROWS) * DIM;
    }
    float s = 0.f;
    #pragma unroll
    for (int k = 0; k < DIM; k += 32) {
        float v = src[k + lane];
        dst[k + lane] = __float2bfloat16_rn(v);
        s = fmaf(v, v, s);
    }
    #pragma unroll
    for (int o = 16; o > 0; o >>= 1) s += __shfl_xor_sync(0xFFFFFFFFu, s, o);
    if (lane == 0) {
        if (warp < N_ROWS) g_zsq[warp] = s;
        else               g_esq[warp - N_ROWS] = s;
    }
}

// ---------------------------------------------------------------------------
// Exact fp32 re-rank with approx-dist prefilter against the FINAL row min.
// Winner survives the filter by construction (d~(j*) <= m~_final + MARGIN).
// ---------------------------------------------------------------------------
__global__ void rerank_kernel(const float* __restrict__ z, const float* __restrict__ cb) {
    unsigned n = g_ncand;
    if (n > CAND_CAP) n = CAND_CAP;
    unsigned stride = gridDim.x * blockDim.x;
    for (unsigned e = blockIdx.x * blockDim.x + threadIdx.x; e < n; e += stride) {
        unsigned long long ent = g_cand[e];
        unsigned key = (unsigned)ent;
        unsigned r = key >> 13;
        unsigned j = key & 8191u;
        float dapprox = __uint_as_float((unsigned)(ent >> 32));
        float cutf = __uint_as_float(g_rowmin[r]) + MARGIN;
        if (dapprox > cutf) continue;        // cannot be the winner

        const float4* zrp = reinterpret_cast<const float4*>(z  + (size_t)r * DIM);
        const float4* crp = reinterpret_cast<const float4*>(cb + (size_t)j * DIM);
        float s = 0.f;
        #pragma unroll 8
        for (int k = 0; k < 64; k++) {
            float4 a = zrp[k];
            float4 b = crp[k];
            s = fmaf(a.x, b.x, s);
            s = fmaf(a.y, b.y, s);
            s = fmaf(a.z, b.z, s);
            s = fmaf(a.w, b.w, s);
        }
        float t = g_zsq[r] + g_esq[j];
        float d = t - 2.0f * s;
        unsigned long long keyv =
            ((unsigned long long)__float_as_uint(d) << 32) | (unsigned long long)j;
        atomicMin(&g_best[r], keyv);
    }
}

__global__ void gather_kernel(const float* __restrict__ z,
                              const float* __restrict__ cb,
                              float* __restrict__ out) {
    __shared__ float wsum[8];
    int warpId = threadIdx.x >> 5;
    int lane   = threadIdx.x & 31;
    int r = blockIdx.x * 8 + warpId;

    unsigned idx = (unsigned)(g_best[r] & 0xFFFFFFFFull);
    const float* zrp = z  + (size_t)r * DIM;
    const float* erp = cb + (size_t)idx * DIM;
    float* orow = out + (size_t)r * DIM;

    float s = 0.f;
    #pragma unroll
    for (int k = 0; k < DIM; k += 32) {
        float zv = zrp[k + lane];
        float ev = erp[k + lane];
        orow[k + lane] = zv + (ev - zv);
        float diff = zv - ev;
        s = fmaf(diff, diff, s);
    }
    #pragma unroll
    for (int o = 16; o > 0; o >>= 1) s += __shfl_xor_sync(0xFFFFFFFFu, s, o);
    if (lane == 0) {
        wsum[warpId] = s;
        out[(size_t)N_ROWS * DIM + r] = (float)idx;
    }
    __syncthreads();
    if (threadIdx.x == 0) {
        float t = 0.f;
        #pragma unroll
        for (int w = 0; w < 8; w++) t += wsum[w];
        g_partial[blockIdx.x] = t;
    }
}

__global__ void loss_kernel(float* __restrict__ out) {
    __shared__ float sm[256];
    int t = threadIdx.x;
    float s = 0.f;
    #pragma unroll
    for (int k = 0; k < G2_BLOCKS; k += 256) s += g_partial[k + t];
    sm[t] = s;
    __syncthreads();
    for (int o = 128; o > 0; o >>= 1) {
        if (t < o) sm[t] = sm[t] + sm[t + o];
        __syncthreads();
    }
    if (t == 0) {
        float m = sm[0] / (float)((size_t)N_ROWS * DIM);
        out[(size_t)N_ROWS * DIM + N_ROWS] = m + 0.25f * m;
    }
}

// ---------------------------------------------------------------------------
// Launch
// ---------------------------------------------------------------------------
extern "C" void kernel_launch(void* const* d_in, const int* in_sizes, int n_in,
                              void* d_out, int out_size) {
    const float* z  = (const float*)d_in[0];
    const float* cb = (const float*)d_in[1];
    float* out = (float*)d_out;
    (void)in_sizes; (void)n_in; (void)out_size;

    cudaFuncSetAttribute(approx_gemm_kernel,
                         cudaFuncAttributeMaxDynamicSharedMemorySize, SMEM_TOTAL);

    init_kernel<<<(N_ROWS + 255) / 256, 256>>>();

    int cs_warps = N_ROWS + K_CODES;                   // 24576 rows
    convsq_kernel<<<(cs_warps * 32 + 255) / 256, 256>>>(z, cb);

    dim3 grid(N_ROWS / BM, YSPLIT);      // (128, 8) = 1024 CTAs
    approx_gemm_kernel<<<grid, 512, SMEM_TOTAL>>>();

    rerank_kernel<<<2048, 256>>>(z, cb);
    gather_kernel<<<G2_BLOCKS, 256>>>(z, cb, out);
    loss_kernel<<<1, 256>>>(out);
}